// round 16
// baseline (speedup 1.0000x reference)
#include <cuda_runtime.h>
#include <cuda_fp16.h>
#include <cstdint>

#define N_NODES 50000
#define N_EDGES 800000
#define D 128
#define CAP 96   // max degree capacity; Poisson(16) => P(deg>96) ~ 0

// ---------------- scratch (device globals; no allocs) ----------------
// g_count is self-cleaning: BSS zero-init at module load; gather re-zeros
// after reading, so every kernel_launch invocation starts from zeros.
__device__ __half g_Y[(size_t)N_NODES * D];      // transformed features, fp16 (12.8 MB)
__device__ int    g_count[N_NODES];
__device__ int    g_slot[(size_t)N_NODES * CAP]; // 19.2 MB

// ---------------------------------------------------------------------------
// Tensor-core GEMM: Y = X @ W^T  (fp16 HMMA, fp32 accumulate, fp16 store)
// BM=64 rows/CTA, 256 threads = 8 warps as 4x2, warp tile 16x64.
// X never touches smem: each thread loads its mma A-fragments directly from
// gmem (32 independent LDG.64 -> huge MLP, DRAM-throughput bound) and
// converts in registers. Only W is staged in smem for ldmatrix.
// W is [out][in] = [n][k] row-major == the B layout mma.row.col wants:
// no transpose, non-trans ldmatrix, pairing {r0,r2}/{r1,r3}.
// smem rows padded to 136 halves (272B): 16B-aligned, ldmatrix conflict-free.
// ---------------------------------------------------------------------------
#define BM 64
#define SPITCH 136   // halves per smem row

__device__ __forceinline__ uint32_t smem_u32(const void* p) {
    return (uint32_t)__cvta_generic_to_shared(p);
}

__device__ __forceinline__ void ldsm_x4(uint32_t addr, uint32_t& r0, uint32_t& r1,
                                        uint32_t& r2, uint32_t& r3) {
    asm volatile("ldmatrix.sync.aligned.m8n8.x4.shared.b16 {%0,%1,%2,%3}, [%4];"
                 : "=r"(r0), "=r"(r1), "=r"(r2), "=r"(r3) : "r"(addr));
}

__device__ __forceinline__ void mma_16816(float* c, uint32_t a0, uint32_t a1,
                                          uint32_t a2, uint32_t a3,
                                          uint32_t b0, uint32_t b1) {
    asm volatile("mma.sync.aligned.m16n8k16.row.col.f32.f16.f16.f32 "
                 "{%0,%1,%2,%3}, {%4,%5,%6,%7}, {%8,%9}, {%0,%1,%2,%3};"
                 : "+f"(c[0]), "+f"(c[1]), "+f"(c[2]), "+f"(c[3])
                 : "r"(a0), "r"(a1), "r"(a2), "r"(a3), "r"(b0), "r"(b1));
}

__device__ __forceinline__ void cvt_store(__half* dstrow, int c4, float4 v) {
    __half2 h01 = __floats2half2_rn(v.x, v.y);
    __half2 h23 = __floats2half2_rn(v.z, v.w);
    uint2 u = { *(uint32_t*)&h01, *(uint32_t*)&h23 };
    *(uint2*)(dstrow + c4 * 4) = u;
}

__global__ void __launch_bounds__(256, 2)
gemm_mma_kernel(const float* __restrict__ X, const float* __restrict__ W) {
    extern __shared__ __half sh[];
    __half* Wh = sh;                      // [128][SPITCH]  rows = n, cols = k

    const int tid  = threadIdx.x;
    const int lane = tid & 31;
    const int wid  = tid >> 5;
    const int row0 = blockIdx.x * BM;

    const int warp_m = (wid & 3) * 16;    // m offset within CTA
    const int warp_n = (wid >> 2) * 64;   // n offset

    // ---- W loads, batch 1 (8 LDG.128 issued early) ----
    const float4* W4 = (const float4*)W;
    float4 wv[8];
#pragma unroll
    for (int i = 0; i < 8; i++) wv[i] = W4[tid + i * 256];

    // ---- A fragments direct from gmem: 32 independent LDG.64 ----
    // mma m16n8k16 A layout: a0=(row grp,   k qc..qc+1)  a1=(row grp+8, qc)
    //                        a2=(row grp,   qc+8)        a3=(row grp+8, qc+8)
    const int grp = lane >> 2;
    const int qc  = (lane & 3) * 2;
    const int r0  = row0 + warp_m + grp;
    const int r1  = r0 + 8;
    const bool v0 = r0 < N_NODES;
    const bool v1 = r1 < N_NODES;
    const float* Xr0 = X + (size_t)r0 * D + qc;
    const float* Xr1 = X + (size_t)r1 * D + qc;

    uint32_t afrag[8][4];
#pragma unroll
    for (int ks = 0; ks < 8; ks++) {
        const int k0 = ks * 16;
        float2 f00 = v0 ? *(const float2*)(Xr0 + k0)     : make_float2(0.f, 0.f);
        float2 f10 = v1 ? *(const float2*)(Xr1 + k0)     : make_float2(0.f, 0.f);
        float2 f01 = v0 ? *(const float2*)(Xr0 + k0 + 8) : make_float2(0.f, 0.f);
        float2 f11 = v1 ? *(const float2*)(Xr1 + k0 + 8) : make_float2(0.f, 0.f);
        __half2 h;
        h = __floats2half2_rn(f00.x, f00.y); afrag[ks][0] = *(uint32_t*)&h;
        h = __floats2half2_rn(f10.x, f10.y); afrag[ks][1] = *(uint32_t*)&h;
        h = __floats2half2_rn(f01.x, f01.y); afrag[ks][2] = *(uint32_t*)&h;
        h = __floats2half2_rn(f11.x, f11.y); afrag[ks][3] = *(uint32_t*)&h;
    }

    // ---- W: convert+store batch 1, load+convert+store batch 2 ----
#pragma unroll
    for (int i = 0; i < 8; i++) {
        int idx = tid + i * 256;
        cvt_store(Wh + (idx >> 5) * SPITCH, idx & 31, wv[i]);
    }
#pragma unroll
    for (int i = 0; i < 8; i++) wv[i] = W4[tid + (i + 8) * 256];
#pragma unroll
    for (int i = 0; i < 8; i++) {
        int idx = tid + (i + 8) * 256;
        cvt_store(Wh + (idx >> 5) * SPITCH, idx & 31, wv[i]);
    }
    __syncthreads();

    float acc[8][4];
#pragma unroll
    for (int n = 0; n < 8; n++)
#pragma unroll
        for (int c = 0; c < 4; c++) acc[n][c] = 0.f;

    const int lrow = lane & 15;           // ldmatrix row within 16
    const int lcol = (lane >> 4) << 3;    // 0 or 8

#pragma unroll
    for (int ks = 0; ks < 8; ks++) {
        const int k0 = ks * 16;

        // B fragments from Wh[n][k], non-trans x4:
        //   r0=(n0-7,k0-7) r1=(n8-15,k0-7) r2=(n0-7,k8-15) r3=(n8-15,k8-15)
        uint32_t b[8][2];
#pragma unroll
        for (int j = 0; j < 4; j++) {
            uint32_t addr = smem_u32(Wh + (warp_n + j * 16 + lrow) * SPITCH + k0 + lcol);
            uint32_t r0f, r1f, r2f, r3f;
            ldsm_x4(addr, r0f, r1f, r2f, r3f);
            b[j * 2][0]     = r0f;  b[j * 2][1]     = r2f;
            b[j * 2 + 1][0] = r1f;  b[j * 2 + 1][1] = r3f;
        }

#pragma unroll
        for (int n = 0; n < 8; n++)
            mma_16816(acc[n], afrag[ks][0], afrag[ks][1], afrag[ks][2], afrag[ks][3],
                      b[n][0], b[n][1]);
    }

    // Epilogue: fp32 acc -> fp16 Y
    const int cpos = (lane & 3) * 2;
#pragma unroll
    for (int n = 0; n < 8; n++) {
        int row = row0 + warp_m + grp;
        int col = warp_n + n * 8 + cpos;
        if (row < N_NODES) {
            __half2 lo = __floats2half2_rn(acc[n][0], acc[n][1]);
            *(__half2*)(g_Y + (size_t)row * D + col) = lo;
        }
        if (row + 8 < N_NODES) {
            __half2 hi = __floats2half2_rn(acc[n][2], acc[n][3]);
            *(__half2*)(g_Y + (size_t)(row + 8) * D + col) = hi;
        }
    }
}

// ---------------------------------------------------------------------------
// Bucket: single pass over edges, slot[dst][pos] = src. 8 edges/thread,
// vectorized int4 loads for both int32 and int64 edge_index layouts.
// ---------------------------------------------------------------------------
__global__ void bucket_kernel(const int* __restrict__ ei) {
    int t  = blockIdx.x * blockDim.x + threadIdx.x;
    int e0 = t * 8;
    if (e0 >= N_EDGES) return;

    bool is64 = ((ei[1] | ei[3] | ei[5] | ei[7]) == 0);

    int src[8], dst[8];
    if (!is64) {
        int4 s0 = *(const int4*)(ei + e0);
        int4 s1 = *(const int4*)(ei + e0 + 4);
        int4 d0 = *(const int4*)(ei + N_EDGES + e0);
        int4 d1 = *(const int4*)(ei + N_EDGES + e0 + 4);
        src[0]=s0.x; src[1]=s0.y; src[2]=s0.z; src[3]=s0.w;
        src[4]=s1.x; src[5]=s1.y; src[6]=s1.z; src[7]=s1.w;
        dst[0]=d0.x; dst[1]=d0.y; dst[2]=d0.z; dst[3]=d0.w;
        dst[4]=d1.x; dst[5]=d1.y; dst[6]=d1.z; dst[7]=d1.w;
    } else {
#pragma unroll
        for (int q = 0; q < 4; q++) {
            int4 a = *(const int4*)(ei + 2 * e0 + q * 4);
            int4 c = *(const int4*)(ei + 2 * (N_EDGES + e0) + q * 4);
            src[q * 2] = a.x; src[q * 2 + 1] = a.z;
            dst[q * 2] = c.x; dst[q * 2 + 1] = c.z;
        }
    }

#pragma unroll
    for (int i = 0; i < 8; i++) {
        int pos = atomicAdd(&g_count[dst[i]], 1);
        if (pos < CAP) g_slot[(size_t)dst[i] * CAP + pos] = src[i];
    }
}

// ---------------------------------------------------------------------------
// Gather: one warp per dst node. lane owns floats [lane*4, lane*4+4).
// Y rows fp16: 8B/lane/row, 8-row unroll (MLP 8), int4 slot loads.
// One-level fp16 pairwise add (HADD2) halves convert+add work; pair sums
// accumulate in fp32. Bias folded; one plain write; re-zeros g_count.
// ---------------------------------------------------------------------------
#define ACCUM(u)  {                                            \
        __half2 h0 = *reinterpret_cast<__half2*>(&(u).x);      \
        __half2 h1 = *reinterpret_cast<__half2*>(&(u).y);      \
        float2 f0 = __half22float2(h0);                        \
        float2 f1 = __half22float2(h1);                        \
        acc.x += f0.x; acc.y += f0.y; acc.z += f1.x; acc.w += f1.y; }

#define HACC(ua, ub) {                                                      \
        __half2 sx = __hadd2(*reinterpret_cast<__half2*>(&(ua).x),          \
                             *reinterpret_cast<__half2*>(&(ub).x));         \
        __half2 sy = __hadd2(*reinterpret_cast<__half2*>(&(ua).y),          \
                             *reinterpret_cast<__half2*>(&(ub).y));         \
        float2 f0 = __half22float2(sx);                                     \
        float2 f1 = __half22float2(sy);                                     \
        acc.x += f0.x; acc.y += f0.y; acc.z += f1.x; acc.w += f1.y; }

__global__ void gather_kernel(const float* __restrict__ b,
                              float4* __restrict__ out4) {
    int node = blockIdx.x * 8 + (threadIdx.x >> 5);
    int lane = threadIdx.x & 31;
    if (node >= N_NODES) return;

    int cnt = g_count[node];
    if (cnt > CAP) cnt = CAP;
    const int* slots = g_slot + (size_t)node * CAP;

    float4 acc = __ldg((const float4*)b + lane);

    int j = 0;
    for (; j + 8 <= cnt; j += 8) {
        int4 sa = *(const int4*)(slots + j);
        int4 sb = *(const int4*)(slots + j + 4);
        uint2 u0 = *(const uint2*)(g_Y + (size_t)sa.x * D + lane * 4);
        uint2 u1 = *(const uint2*)(g_Y + (size_t)sa.y * D + lane * 4);
        uint2 u2 = *(const uint2*)(g_Y + (size_t)sa.z * D + lane * 4);
        uint2 u3 = *(const uint2*)(g_Y + (size_t)sa.w * D + lane * 4);
        uint2 u4 = *(const uint2*)(g_Y + (size_t)sb.x * D + lane * 4);
        uint2 u5 = *(const uint2*)(g_Y + (size_t)sb.y * D + lane * 4);
        uint2 u6 = *(const uint2*)(g_Y + (size_t)sb.z * D + lane * 4);
        uint2 u7 = *(const uint2*)(g_Y + (size_t)sb.w * D + lane * 4);
        HACC(u0, u1); HACC(u2, u3); HACC(u4, u5); HACC(u6, u7);
    }
    if (j + 4 <= cnt) {
        int4 sa = *(const int4*)(slots + j);
        uint2 u0 = *(const uint2*)(g_Y + (size_t)sa.x * D + lane * 4);
        uint2 u1 = *(const uint2*)(g_Y + (size_t)sa.y * D + lane * 4);
        uint2 u2 = *(const uint2*)(g_Y + (size_t)sa.z * D + lane * 4);
        uint2 u3 = *(const uint2*)(g_Y + (size_t)sa.w * D + lane * 4);
        HACC(u0, u1); HACC(u2, u3);
        j += 4;
    }
    for (; j < cnt; j++) {
        uint2 u = *(const uint2*)(g_Y + (size_t)slots[j] * D + lane * 4);
        ACCUM(u);
    }

    out4[(size_t)node * 32 + lane] = acc;

    // self-clean for the next invocation (state at entry is always zero)
    if (lane == 0) g_count[node] = 0;
}
#undef ACCUM
#undef HACC

// ---------------------------------------------------------------------------
// Launch: gemm(mma) -> bucket -> gather   (3 kernels)
// ---------------------------------------------------------------------------
extern "C" void kernel_launch(void* const* d_in, const int* in_sizes, int n_in,
                              void* d_out, int out_size) {
    const float* X  = (const float*)d_in[0];
    const int*   EI = (const int*)d_in[1];
    const float* W  = (const float*)d_in[2];
    const float* B  = (const float*)d_in[3];
    float*       O  = (float*)d_out;

    const int smem_bytes = D * SPITCH * sizeof(__half);   // ~35 KB (W only)
    cudaFuncSetAttribute(gemm_mma_kernel,
                         cudaFuncAttributeMaxDynamicSharedMemorySize, smem_bytes);
    gemm_mma_kernel<<<(N_NODES + BM - 1) / BM, 256, smem_bytes>>>(X, W);

    bucket_kernel<<<(N_EDGES / 8 + 255) / 256, 256>>>(EI);

    gather_kernel<<<(N_NODES + 7) / 8, 256>>>(B, (float4*)O);
}

// round 17
// speedup vs baseline: 1.0012x; 1.0012x over previous
#include <cuda_runtime.h>
#include <cuda_fp16.h>
#include <cstdint>

#define N_NODES 50000
#define N_EDGES 800000
#define D 128
#define CAP 96   // max degree capacity; Poisson(16) => P(deg>96) ~ 0

#define GEMM_BLOCKS 782   // ceil(50000/64)
#define BUCKET_BLOCKS 391 // ceil(800000/(256*8))
#define TOTAL_BLOCKS (GEMM_BLOCKS + BUCKET_BLOCKS)  // 1173 = 3*391

// ---------------- scratch (device globals; no allocs) ----------------
// g_count is self-cleaning: BSS zero-init at module load; gather re-zeros
// after reading, so every kernel_launch invocation starts from zeros.
__device__ __half g_Y[(size_t)N_NODES * D];      // transformed features, fp16 (12.8 MB)
__device__ int    g_count[N_NODES];
__device__ int    g_slot[(size_t)N_NODES * CAP]; // 19.2 MB

#define BM 64
#define SPITCH 136   // halves per smem row (272B: 16B-aligned, ldsm conflict-free)

__device__ __forceinline__ uint32_t smem_u32(const void* p) {
    return (uint32_t)__cvta_generic_to_shared(p);
}

__device__ __forceinline__ void ldsm_x4(uint32_t addr, uint32_t& r0, uint32_t& r1,
                                        uint32_t& r2, uint32_t& r3) {
    asm volatile("ldmatrix.sync.aligned.m8n8.x4.shared.b16 {%0,%1,%2,%3}, [%4];"
                 : "=r"(r0), "=r"(r1), "=r"(r2), "=r"(r3) : "r"(addr));
}

__device__ __forceinline__ void mma_16816(float* c, uint32_t a0, uint32_t a1,
                                          uint32_t a2, uint32_t a3,
                                          uint32_t b0, uint32_t b1) {
    asm volatile("mma.sync.aligned.m16n8k16.row.col.f32.f16.f16.f32 "
                 "{%0,%1,%2,%3}, {%4,%5,%6,%7}, {%8,%9}, {%0,%1,%2,%3};"
                 : "+f"(c[0]), "+f"(c[1]), "+f"(c[2]), "+f"(c[3])
                 : "r"(a0), "r"(a1), "r"(a2), "r"(a3), "r"(b0), "r"(b1));
}

__device__ __forceinline__ void cvt_store(__half* dstrow, int c4, float4 v) {
    __half2 h01 = __floats2half2_rn(v.x, v.y);
    __half2 h23 = __floats2half2_rn(v.z, v.w);
    uint2 u = { *(uint32_t*)&h01, *(uint32_t*)&h23 };
    *(uint2*)(dstrow + c4 * 4) = u;
}

// ---------------------------------------------------------------------------
// GEMM block body: Y[row0..row0+64) = X @ W^T  (R15 structure: X+W via smem,
// MLP-8 staged loads, 8 warps as 4x2, warp tile 16x64, fp32 acc, fp16 store).
// W is [out][in] = [n][k] row-major == B layout for mma.row.col: non-trans
// ldmatrix, fragment pairing {r0,r2}/{r1,r3}.
// ---------------------------------------------------------------------------
__device__ __forceinline__ void gemm_block(const float* __restrict__ X,
                                           const float* __restrict__ W,
                                           int gemm_bid) {
    extern __shared__ __half sh[];
    __half* Xh = sh;                      // [BM][SPITCH]   rows = m, cols = k
    __half* Wh = sh + BM * SPITCH;        // [128][SPITCH]  rows = n, cols = k

    const int tid  = threadIdx.x;
    const int lane = tid & 31;
    const int wid  = tid >> 5;
    const int row0 = gemm_bid * BM;

    // ---- staged loads: issue all LDGs, then convert+STS (MLP 8) ----
    {
        const float4* X4 = (const float4*)(X + (size_t)row0 * D);
        int nrows = N_NODES - row0;
        if (nrows > BM) nrows = BM;
        float4 xv[8];
#pragma unroll
        for (int i = 0; i < 8; i++) {
            int idx = tid + i * 256;
            int r = idx >> 5;
            xv[i] = (r < nrows) ? X4[idx] : make_float4(0.f, 0.f, 0.f, 0.f);
        }
        const float4* W4 = (const float4*)W;
        float4 wv[8];
#pragma unroll
        for (int i = 0; i < 8; i++) wv[i] = W4[tid + i * 256];
#pragma unroll
        for (int i = 0; i < 8; i++) {
            int idx = tid + i * 256;
            cvt_store(Xh + (idx >> 5) * SPITCH, idx & 31, xv[i]);
        }
#pragma unroll
        for (int i = 0; i < 8; i++) {
            int idx = tid + i * 256;
            cvt_store(Wh + (idx >> 5) * SPITCH, idx & 31, wv[i]);
        }
#pragma unroll
        for (int i = 0; i < 8; i++) wv[i] = W4[tid + (i + 8) * 256];
#pragma unroll
        for (int i = 0; i < 8; i++) {
            int idx = tid + (i + 8) * 256;
            cvt_store(Wh + (idx >> 5) * SPITCH, idx & 31, wv[i]);
        }
    }
    __syncthreads();

    const int warp_m = (wid & 3) * 16;
    const int warp_n = (wid >> 2) * 64;

    float acc[8][4];
#pragma unroll
    for (int n = 0; n < 8; n++)
#pragma unroll
        for (int c = 0; c < 4; c++) acc[n][c] = 0.f;

    const int lrow = lane & 15;
    const int lcol = (lane >> 4) << 3;

#pragma unroll
    for (int ks = 0; ks < 8; ks++) {
        const int k0 = ks * 16;

        uint32_t a0, a1, a2, a3;
        {
            uint32_t addr = smem_u32(Xh + (warp_m + lrow) * SPITCH + k0 + lcol);
            ldsm_x4(addr, a0, a1, a2, a3);
        }

        uint32_t b[8][2];
#pragma unroll
        for (int j = 0; j < 4; j++) {
            uint32_t addr = smem_u32(Wh + (warp_n + j * 16 + lrow) * SPITCH + k0 + lcol);
            uint32_t r0, r1, r2, r3;
            ldsm_x4(addr, r0, r1, r2, r3);
            b[j * 2][0]     = r0;  b[j * 2][1]     = r2;
            b[j * 2 + 1][0] = r1;  b[j * 2 + 1][1] = r3;
        }

#pragma unroll
        for (int n = 0; n < 8; n++)
            mma_16816(acc[n], a0, a1, a2, a3, b[n][0], b[n][1]);
    }

    const int grp  = lane >> 2;
    const int cpos = (lane & 3) * 2;
#pragma unroll
    for (int n = 0; n < 8; n++) {
        int row = row0 + warp_m + grp;
        int col = warp_n + n * 8 + cpos;
        if (row < N_NODES) {
            __half2 lo = __floats2half2_rn(acc[n][0], acc[n][1]);
            *(__half2*)(g_Y + (size_t)row * D + col) = lo;
        }
        if (row + 8 < N_NODES) {
            __half2 hi = __floats2half2_rn(acc[n][2], acc[n][3]);
            *(__half2*)(g_Y + (size_t)(row + 8) * D + col) = hi;
        }
    }
}

// ---------------------------------------------------------------------------
// Bucket block body: slot[dst][pos] = src for 256*8 edges.
// Vectorized int4 loads; dtype sniff (int64 with values<50000 -> odd words 0).
// ---------------------------------------------------------------------------
__device__ __forceinline__ void bucket_block(const int* __restrict__ ei,
                                             int bucket_bid) {
    int t  = bucket_bid * 256 + threadIdx.x;
    int e0 = t * 8;
    if (e0 >= N_EDGES) return;

    bool is64 = ((ei[1] | ei[3] | ei[5] | ei[7]) == 0);

    int src[8], dst[8];
    if (!is64) {
        int4 s0 = *(const int4*)(ei + e0);
        int4 s1 = *(const int4*)(ei + e0 + 4);
        int4 d0 = *(const int4*)(ei + N_EDGES + e0);
        int4 d1 = *(const int4*)(ei + N_EDGES + e0 + 4);
        src[0]=s0.x; src[1]=s0.y; src[2]=s0.z; src[3]=s0.w;
        src[4]=s1.x; src[5]=s1.y; src[6]=s1.z; src[7]=s1.w;
        dst[0]=d0.x; dst[1]=d0.y; dst[2]=d0.z; dst[3]=d0.w;
        dst[4]=d1.x; dst[5]=d1.y; dst[6]=d1.z; dst[7]=d1.w;
    } else {
#pragma unroll
        for (int q = 0; q < 4; q++) {
            int4 a = *(const int4*)(ei + 2 * e0 + q * 4);
            int4 c = *(const int4*)(ei + 2 * (N_EDGES + e0) + q * 4);
            src[q * 2] = a.x; src[q * 2 + 1] = a.z;
            dst[q * 2] = c.x; dst[q * 2 + 1] = c.z;
        }
    }

#pragma unroll
    for (int i = 0; i < 8; i++) {
        int pos = atomicAdd(&g_count[dst[i]], 1);
        if (pos < CAP) g_slot[(size_t)dst[i] * CAP + pos] = src[i];
    }
}

// ---------------------------------------------------------------------------
// Fused GEMM + bucket: 1173 blocks, role by idx%3 (2/3 gemm, 1/3 bucket)
// so every scheduling wave mixes memory-latency (gemm) and atomic-latency
// (bucket) blocks. Bodies touch disjoint data.
// ---------------------------------------------------------------------------
__global__ void __launch_bounds__(256, 4)
fused_gemm_bucket_kernel(const float* __restrict__ X,
                         const float* __restrict__ W,
                         const int* __restrict__ ei) {
    int b = blockIdx.x;
    int grp = b / 3, rem = b - grp * 3;
    if (rem < 2) {
        gemm_block(X, W, grp * 2 + rem);
    } else {
        bucket_block(ei, grp);
    }
}

// ---------------------------------------------------------------------------
// Gather: one warp per dst node. lane owns floats [lane*4, lane*4+4).
// Y rows fp16: 8B/lane/row, 8-row unroll (MLP 8), int4 slot loads.
// One-level fp16 pairwise add (HADD2); pair sums accumulate in fp32.
// Bias folded; one plain write; re-zeros g_count.
// ---------------------------------------------------------------------------
#define ACCUM(u)  {                                            \
        __half2 h0 = *reinterpret_cast<__half2*>(&(u).x);      \
        __half2 h1 = *reinterpret_cast<__half2*>(&(u).y);      \
        float2 f0 = __half22float2(h0);                        \
        float2 f1 = __half22float2(h1);                        \
        acc.x += f0.x; acc.y += f0.y; acc.z += f1.x; acc.w += f1.y; }

#define HACC(ua, ub) {                                                      \
        __half2 sx = __hadd2(*reinterpret_cast<__half2*>(&(ua).x),          \
                             *reinterpret_cast<__half2*>(&(ub).x));         \
        __half2 sy = __hadd2(*reinterpret_cast<__half2*>(&(ua).y),          \
                             *reinterpret_cast<__half2*>(&(ub).y));         \
        float2 f0 = __half22float2(sx);                                     \
        float2 f1 = __half22float2(sy);                                     \
        acc.x += f0.x; acc.y += f0.y; acc.z += f1.x; acc.w += f1.y; }

__global__ void gather_kernel(const float* __restrict__ b,
                              float4* __restrict__ out4) {
    int node = blockIdx.x * 8 + (threadIdx.x >> 5);
    int lane = threadIdx.x & 31;
    if (node >= N_NODES) return;

    int cnt = g_count[node];
    if (cnt > CAP) cnt = CAP;
    const int* slots = g_slot + (size_t)node * CAP;

    float4 acc = __ldg((const float4*)b + lane);

    int j = 0;
    for (; j + 8 <= cnt; j += 8) {
        int4 sa = *(const int4*)(slots + j);
        int4 sb = *(const int4*)(slots + j + 4);
        uint2 u0 = *(const uint2*)(g_Y + (size_t)sa.x * D + lane * 4);
        uint2 u1 = *(const uint2*)(g_Y + (size_t)sa.y * D + lane * 4);
        uint2 u2 = *(const uint2*)(g_Y + (size_t)sa.z * D + lane * 4);
        uint2 u3 = *(const uint2*)(g_Y + (size_t)sa.w * D + lane * 4);
        uint2 u4 = *(const uint2*)(g_Y + (size_t)sb.x * D + lane * 4);
        uint2 u5 = *(const uint2*)(g_Y + (size_t)sb.y * D + lane * 4);
        uint2 u6 = *(const uint2*)(g_Y + (size_t)sb.z * D + lane * 4);
        uint2 u7 = *(const uint2*)(g_Y + (size_t)sb.w * D + lane * 4);
        HACC(u0, u1); HACC(u2, u3); HACC(u4, u5); HACC(u6, u7);
    }
    if (j + 4 <= cnt) {
        int4 sa = *(const int4*)(slots + j);
        uint2 u0 = *(const uint2*)(g_Y + (size_t)sa.x * D + lane * 4);
        uint2 u1 = *(const uint2*)(g_Y + (size_t)sa.y * D + lane * 4);
        uint2 u2 = *(const uint2*)(g_Y + (size_t)sa.z * D + lane * 4);
        uint2 u3 = *(const uint2*)(g_Y + (size_t)sa.w * D + lane * 4);
        HACC(u0, u1); HACC(u2, u3);
        j += 4;
    }
    for (; j < cnt; j++) {
        uint2 u = *(const uint2*)(g_Y + (size_t)slots[j] * D + lane * 4);
        ACCUM(u);
    }

    out4[(size_t)node * 32 + lane] = acc;

    // self-clean for the next invocation (state at entry is always zero)
    if (lane == 0) g_count[node] = 0;
}
#undef ACCUM
#undef HACC

// ---------------------------------------------------------------------------
// Launch: fused(gemm+bucket) -> gather   (2 kernels)
// ---------------------------------------------------------------------------
extern "C" void kernel_launch(void* const* d_in, const int* in_sizes, int n_in,
                              void* d_out, int out_size) {
    const float* X  = (const float*)d_in[0];
    const int*   EI = (const int*)d_in[1];
    const float* W  = (const float*)d_in[2];
    const float* B  = (const float*)d_in[3];
    float*       O  = (float*)d_out;

    const int smem_bytes = (BM + D) * SPITCH * sizeof(__half);   // ~52 KB
    cudaFuncSetAttribute(fused_gemm_bucket_kernel,
                         cudaFuncAttributeMaxDynamicSharedMemorySize, smem_bytes);
    fused_gemm_bucket_kernel<<<TOTAL_BLOCKS, 256, smem_bytes>>>(X, W, EI);

    gather_kernel<<<(N_NODES + 7) / 8, 256>>>(B, (float4*)O);
}